// round 17
// baseline (speedup 1.0000x reference)
#include <cuda_runtime.h>
#include <cuda_fp16.h>
#include <cstdint>

#define HEADS 16
#define HID   1024
#define DH    64
#define BATCH 2
#define SEQ   2048
#define MROWS (BATCH*SEQ)
#define KDIM  1024

// ---------------- scratch (__device__ globals; alloc-free rule) -------------
__device__ __half g_Q[(size_t)BATCH*HEADS*SEQ*DH];
__device__ __half g_K[(size_t)BATCH*HEADS*SEQ*DH];
__device__ __half g_V[(size_t)BATCH*HEADS*SEQ*DH];

__device__ __half g_X [(size_t)MROWS*HID];
__device__ __half g_O [(size_t)MROWS*HID];
__device__ __half g_Wt[(size_t)4*HID*HID];
__device__ __half g_Mc[BATCH*SEQ];
__device__ int    g_Idx[BATCH*SEQ];
__device__ int    g_Cnt[BATCH];

// unified sync array (zeroed by cudaMemsetAsync each call):
// [0] prepass count (256) | [1],[2] KV counts (256) | [3..258] Q flags | [259..290] O counts
__device__ int    g_Sync[512];

// ---------------- PTX helpers ------------------------------------------------
__device__ __forceinline__ uint32_t smem_u32(const void* p) {
    uint32_t a;
    asm("{ .reg .u64 t; cvta.to.shared.u64 t, %1; cvt.u32.u64 %0, t; }"
        : "=r"(a) : "l"(p));
    return a;
}
__device__ __forceinline__ void cpa16(uint32_t dst, const void* src) {
    asm volatile("cp.async.cg.shared.global [%0], [%1], 16;"
                 :: "r"(dst), "l"(src));
}
__device__ __forceinline__ void cpa16z(uint32_t dst, const void* src, uint32_t n) {
    asm volatile("cp.async.cg.shared.global [%0], [%1], 16, %2;"
                 :: "r"(dst), "l"(src), "r"(n));
}
#define CPA_COMMIT() asm volatile("cp.async.commit_group;" ::: "memory")
#define CPA_WAIT(n)  asm volatile("cp.async.wait_group %0;" :: "n"(n) : "memory")

__device__ __forceinline__ void ldsm4(uint32_t r[4], uint32_t addr) {
    asm volatile("ldmatrix.sync.aligned.m8n8.x4.shared.b16 {%0,%1,%2,%3}, [%4];"
                 : "=r"(r[0]), "=r"(r[1]), "=r"(r[2]), "=r"(r[3]) : "r"(addr));
}
__device__ __forceinline__ void ldsm4t(uint32_t r[4], uint32_t addr) {
    asm volatile("ldmatrix.sync.aligned.m8n8.x4.trans.shared.b16 {%0,%1,%2,%3}, [%4];"
                 : "=r"(r[0]), "=r"(r[1]), "=r"(r[2]), "=r"(r[3]) : "r"(addr));
}
__device__ __forceinline__ void ldsm2t(uint32_t r[2], uint32_t addr) {
    asm volatile("ldmatrix.sync.aligned.m8n8.x2.trans.shared.b16 {%0,%1}, [%2];"
                 : "=r"(r[0]), "=r"(r[1]) : "r"(addr));
}
__device__ __forceinline__ void mma_f16(float c[4], const uint32_t a[4],
                                        uint32_t b0, uint32_t b1) {
    asm volatile(
        "mma.sync.aligned.m16n8k16.row.col.f32.f16.f16.f32 "
        "{%0,%1,%2,%3}, {%4,%5,%6,%7}, {%8,%9}, {%0,%1,%2,%3};"
        : "+f"(c[0]), "+f"(c[1]), "+f"(c[2]), "+f"(c[3])
        : "r"(a[0]), "r"(a[1]), "r"(a[2]), "r"(a[3]), "r"(b0), "r"(b1));
}
__device__ __forceinline__ uint32_t packh(float v0, float v1) {
    uint32_t d;
    asm("cvt.rn.f16x2.f32 %0, %1, %2;" : "=r"(d) : "f"(v1), "f"(v0));
    return d;
}
__device__ __forceinline__ uint32_t ex2h2(uint32_t x) {
    uint32_t y;
    asm("ex2.approx.f16x2 %0, %1;" : "=r"(y) : "r"(x));
    return y;
}
__device__ __forceinline__ uint32_t hmul2(uint32_t a, uint32_t b) {
    uint32_t d;
    asm("mul.f16x2 %0, %1, %2;" : "=r"(d) : "r"(a), "r"(b));
    return d;
}
__device__ __forceinline__ void spin_ge(const int* p, int target) {
    int v;
    while (true) {
        asm volatile("ld.acquire.gpu.s32 %0, [%1];" : "=r"(v) : "l"(p) : "memory");
        if (v >= target) break;
        __nanosleep(128);
    }
}
#define SWZ(o) ((o) ^ ((((uint32_t)(o)) >> 3) & 0x70u))

#define LOG2E      1.4426950408889634f
#define SCALE_L2   (0.125f * LOG2E)

// ---------------- fp16 GEMM body: 128 thr, 4 warps x (64x64), K-chunk 64 ----
#define LDA        72
#define PART_BYTES (128 * LDA * 2)
#define BUF_BYTES  (2 * PART_BYTES)
#define GEMM_SMEM  (2 * BUF_BYTES)   // 73728

__device__ __forceinline__ void hmma_gemm(
    const __half* __restrict__ A, const __half* __restrict__ B,
    const float* __restrict__ bias, float escale, float* __restrict__ C,
    __half* __restrict__ Ch, int mode, int row0, int col0,
    const int* __restrict__ idxp, int cnt)
{
    extern __shared__ char sm[];
    const uint32_t sbase = smem_u32(sm);
    const int tid  = threadIdx.x;
    const int wid  = tid >> 5, lane = tid & 31;
    const int warp_m = wid >> 1;
    const int warp_n = wid & 1;

    const int rthr = tid >> 3;
    const int seg  = tid & 7;
    uint32_t aoff[8];
    uint32_t asz[8];
    #pragma unroll
    for (int it = 0; it < 8; ++it) {
        const int r = row0 + rthr + it * 16;
        if (idxp) {
            aoff[it] = (uint32_t)idxp[r] * (KDIM * 2) + seg * 16;
            asz[it]  = (r < cnt) ? 16u : 0u;
        } else {
            aoff[it] = (uint32_t)r * (KDIM * 2) + seg * 16;
            asz[it]  = 16u;
        }
    }
    const __half* Bp = B + (size_t)col0 * KDIM;

    auto load_chunk = [&](int chunk, int buf) {
        const int k0b = chunk * 128;
        const uint32_t dbaseA = sbase + buf * BUF_BYTES;
        #pragma unroll
        for (int it = 0; it < 8; ++it) {
            const int row = rthr + it * 16;
            cpa16z(dbaseA + (uint32_t)row * (LDA * 2) + seg * 16,
                   (const char*)A + aoff[it] + k0b, asz[it]);
        }
        const uint32_t dbaseB = dbaseA + PART_BYTES;
        #pragma unroll
        for (int it = 0; it < 8; ++it) {
            const int row = rthr + it * 16;
            cpa16(dbaseB + (uint32_t)row * (LDA * 2) + seg * 16,
                  (const char*)Bp + (size_t)row * (KDIM * 2) + seg * 16 + k0b);
        }
        CPA_COMMIT();
    };

    float c[4][8][4];
    #pragma unroll
    for (int mf = 0; mf < 4; mf++)
        #pragma unroll
        for (int nf = 0; nf < 8; nf++)
            #pragma unroll
            for (int j = 0; j < 4; j++) c[mf][nf][j] = 0.0f;

    load_chunk(0, 0);
    int buf = 0;

    for (int i = 0; i < KDIM / 64; ++i) {
        if (i + 1 < KDIM / 64) {
            load_chunk(i + 1, buf ^ 1);
            CPA_WAIT(1);
        } else {
            CPA_WAIT(0);
        }
        __syncthreads();

        const uint32_t base = sbase + buf * BUF_BYTES;
        #pragma unroll
        for (int ks = 0; ks < 64; ks += 16) {
            uint32_t ah[4][4];
            #pragma unroll
            for (int mf = 0; mf < 4; mf++) {
                int row = warp_m * 64 + mf * 16 + (lane & 15);
                int col = ks + ((lane & 16) ? 8 : 0);
                ldsm4(ah[mf], base + (uint32_t)row * (LDA * 2) + col * 2);
            }
            #pragma unroll
            for (int nf4 = 0; nf4 < 4; nf4++) {
                int nrow = warp_n * 64 + nf4 * 16 + (lane & 7) + ((lane & 16) ? 8 : 0);
                int col  = ks + ((lane & 8) ? 8 : 0);
                uint32_t tb[4];
                ldsm4(tb, base + PART_BYTES + (uint32_t)nrow * (LDA * 2) + col * 2);
                const int j = 2 * nf4;
                #pragma unroll
                for (int mf = 0; mf < 4; mf++) {
                    mma_f16(c[mf][j],   ah[mf], tb[0], tb[1]);
                    mma_f16(c[mf][j+1], ah[mf], tb[2], tb[3]);
                }
            }
        }
        __syncthreads();
        buf ^= 1;
    }

    const int rbase = row0 + warp_m * 64 + (lane >> 2);
    const int cbase = col0 + warp_n * 64 + 2 * (lane & 3);
    #pragma unroll
    for (int mf = 0; mf < 4; mf++) {
        #pragma unroll
        for (int nf = 0; nf < 8; nf++) {
            const int gc = cbase + nf * 8;
            const float b0 = bias[gc], b1 = bias[gc + 1];
            #pragma unroll
            for (int half = 0; half < 2; half++) {
                const int gr = rbase + mf * 16 + half * 8;
                float v0 = (c[mf][nf][half*2]   + b0) * escale;
                float v1 = (c[mf][nf][half*2+1] + b1) * escale;
                if (mode == 0) {
                    float* dst = C + (size_t)gr * HID + gc;
                    *(float2*)dst = make_float2(v0, v1);
                } else {
                    const int h = gc >> 6;
                    const int d = gc & 63;
                    size_t off;
                    if (mode == 1) {
                        const int bb = gr >> 11;
                        const int lq = gr & (SEQ - 1);
                        off = ((size_t)((bb * HEADS + h) * SEQ + lq)) * DH + d;
                    } else {
                        off = ((size_t)(h * SEQ + gr)) * DH + d;
                    }
                    *(uint32_t*)(Ch + off) = packh(v0, v1);
                }
            }
        }
    }
}

// ---------------- attention body (q-tile 128) --------------------------------
#define ATT_LDS   72
#define ATT_PART  (64 * ATT_LDS * 2)
#define ATT_BUF   (2 * ATT_PART)
#define ATT_Q     16384
#define ATT_MASK  (ATT_Q + 2 * ATT_BUF)
#define ATT_THR   128

__device__ __forceinline__ void attn_body(int b, int h, int q0)
{
    extern __shared__ char sm[];
    const uint32_t sbase = smem_u32(sm);
    const int tid  = threadIdx.x;
    const int wid  = tid >> 5, lane = tid & 31;

    const int cnt = g_Cnt[b];
    const int nkt = (cnt + 63) >> 6;

    const size_t bh_off = (size_t)(b * HEADS + h) * SEQ * DH;
    const __half* Qg = g_Q + bh_off + (size_t)q0 * DH;
    const __half* Kg = g_K + bh_off;
    const __half* Vg = g_V + bh_off;
    const __half* mrow = g_Mc + (size_t)b * SEQ;

    auto load_tile = [&](int i, int buf) {
        const int k0 = i * 64;
        const __half* srcs[2] = { Kg + (size_t)k0 * DH, Vg + (size_t)k0 * DH };
        #pragma unroll
        for (int p = 0; p < 2; ++p) {
            const uint32_t base = sbase + ATT_Q + buf * ATT_BUF + p * ATT_PART;
            #pragma unroll
            for (int it = 0; it < 4; ++it) {
                int idx = tid + it * ATT_THR;
                int row = idx >> 3;
                int seg = idx & 7;
                cpa16(base + (uint32_t)row * (ATT_LDS * 2) + seg * 16,
                      srcs[p] + (size_t)row * DH + seg * 8);
            }
        }
        if (tid < 8)
            cpa16(sbase + ATT_MASK + buf * 128 + tid * 16, mrow + k0 + tid * 8);
        CPA_COMMIT();
    };

    {
        int bufi = tid >> 6;
        int row  = tid & 63;
        uint4* p = (uint4*)(sm + ATT_Q + bufi * ATT_BUF + ATT_PART
                            + row * (ATT_LDS * 2) + 128);
        *p = make_uint4(0x00003C00u, 0u, 0u, 0u);
    }

    {
        #pragma unroll
        for (int it = 0; it < 8; ++it) {
            int idx = tid + it * ATT_THR;
            int row = idx >> 3;
            int seg = idx & 7;
            cpa16(sbase + SWZ((uint32_t)row * 128 + seg * 16),
                  Qg + (size_t)row * DH + seg * 8);
        }
        CPA_COMMIT();
    }
    load_tile(0, 0);
    CPA_WAIT(0);
    __syncthreads();

    uint32_t qf[2][4][4];
    #pragma unroll
    for (int t = 0; t < 4; ++t)
        #pragma unroll
        for (int mf = 0; mf < 2; mf++) {
            const int row = wid * 32 + mf * 16 + (lane & 15);
            const uint32_t colb = (uint32_t)(t * 16 + ((lane & 16) ? 8 : 0)) * 2;
            ldsm4(qf[mf][t], sbase + SWZ((uint32_t)row * 128 + colb));
        }

    uint32_t eones[2];
    {
        const int krow = lane & 15;
        ldsm2t(eones, sbase + ATT_Q + ATT_PART + (uint32_t)krow * (ATT_LDS * 2) + 128);
    }

    float o[2][8][4];
    float oE[2][4];
    #pragma unroll
    for (int mf = 0; mf < 2; mf++) {
        #pragma unroll
        for (int j = 0; j < 8; j++)
            #pragma unroll
            for (int cc = 0; cc < 4; cc++) o[mf][j][cc] = 0.0f;
        #pragma unroll
        for (int cc = 0; cc < 4; cc++) oE[mf][cc] = 0.0f;
    }

    for (int i = 0; i < nkt; ++i) {
        const int buf = i & 1;
        if (i + 1 < nkt) {
            load_tile(i + 1, buf ^ 1);
            CPA_WAIT(1);
        } else {
            CPA_WAIT(0);
        }
        __syncthreads();

        const uint32_t kbase = sbase + ATT_Q + buf * ATT_BUF;

        float s[2][8][4];
        #pragma unroll
        for (int mf = 0; mf < 2; mf++)
            #pragma unroll
            for (int j = 0; j < 8; j++)
                #pragma unroll
                for (int cc = 0; cc < 4; cc++) s[mf][j][cc] = 0.0f;

        #pragma unroll
        for (int t = 0; t < 4; ++t) {
            #pragma unroll
            for (int nf2 = 0; nf2 < 4; ++nf2) {
                const int nrow = nf2 * 16 + (lane & 7) + ((lane & 16) ? 8 : 0);
                const uint32_t colb = (uint32_t)(t * 16 + ((lane & 8) ? 8 : 0)) * 2;
                uint32_t th[4];
                ldsm4(th, kbase + (uint32_t)nrow * (ATT_LDS * 2) + colb);
                const int j = 2 * nf2;
                #pragma unroll
                for (int mf = 0; mf < 2; mf++) {
                    mma_f16(s[mf][j],   qf[mf][t], th[0], th[1]);
                    mma_f16(s[mf][j+1], qf[mf][t], th[2], th[3]);
                }
            }
        }

        uint32_t ph[2][8][2];
        uint32_t mh[8];
        #pragma unroll
        for (int j = 0; j < 8; j++)
            mh[j] = *(const uint32_t*)(sm + ATT_MASK + buf * 128
                                       + (8 * j + 2 * (lane & 3)) * 2);
        #pragma unroll
        for (int mf = 0; mf < 2; mf++)
            #pragma unroll
            for (int j = 0; j < 8; j++) {
                ph[mf][j][0] = hmul2(ex2h2(packh(s[mf][j][0], s[mf][j][1])), mh[j]);
                ph[mf][j][1] = hmul2(ex2h2(packh(s[mf][j][2], s[mf][j][3])), mh[j]);
            }

        #pragma unroll
        for (int t = 0; t < 4; ++t) {
            uint32_t a0[4] = { ph[0][2*t][0], ph[0][2*t][1],
                               ph[0][2*t+1][0], ph[0][2*t+1][1] };
            uint32_t a1[4] = { ph[1][2*t][0], ph[1][2*t][1],
                               ph[1][2*t+1][0], ph[1][2*t+1][1] };
            mma_f16(oE[0], a0, eones[0], eones[1]);
            mma_f16(oE[1], a1, eones[0], eones[1]);
            #pragma unroll
            for (int nf2 = 0; nf2 < 4; ++nf2) {
                const int krow = t * 16 + (lane & 15);
                const uint32_t colb = (uint32_t)(nf2 * 16 + ((lane & 16) ? 8 : 0)) * 2;
                uint32_t tv[4];
                ldsm4t(tv, kbase + ATT_PART + (uint32_t)krow * (ATT_LDS * 2) + colb);
                const int j = 2 * nf2;
                mma_f16(o[0][j],   a0, tv[0], tv[1]);
                mma_f16(o[0][j+1], a0, tv[2], tv[3]);
                mma_f16(o[1][j],   a1, tv[0], tv[1]);
                mma_f16(o[1][j+1], a1, tv[2], tv[3]);
            }
        }
        __syncthreads();
    }

    #pragma unroll
    for (int mf = 0; mf < 2; mf++) {
        const float l0 = __shfl_sync(0xffffffffu, oE[mf][0], lane & ~3);
        const float l1 = __shfl_sync(0xffffffffu, oE[mf][2], lane & ~3);
        const float inv0 = 1.0f / l0;
        const float inv1 = 1.0f / l1;
        const int r0 = q0 + wid * 32 + mf * 16 + (lane >> 2);
        #pragma unroll
        for (int j = 0; j < 8; j++) {
            const int col = h * 64 + 8 * j + 2 * (lane & 3);
            #pragma unroll
            for (int half = 0; half < 2; half++) {
                const int gr = r0 + half * 8;
                const float inv = half ? inv1 : inv0;
                float v0 = o[mf][j][half*2]     * inv;
                float v1 = o[mf][j][half*2 + 1] * inv;
                size_t off = (size_t)(b * SEQ + gr) * HID + col;
                *(uint32_t*)(g_O + off) = packh(v0, v1);
            }
        }
    }
}

// ---------------- prepass body: compact + W transpose + X convert -----------
__device__ __forceinline__ void prepass_body(
    int bid, const float* __restrict__ x, const float* __restrict__ mask,
    const float* __restrict__ Wq, const float* __restrict__ Wk,
    const float* __restrict__ Wv, const float* __restrict__ Wo)
{
    extern __shared__ char sm[];
    const int tid = threadIdx.x;

    // ---- compaction (bids 0,1) ----
    if (bid < BATCH) {
        int* cnts = (int*)sm;   // 128 ints
        const int b = bid;
        const float* m = mask + (size_t)b * SEQ;
        int keep[16];
        int c = 0;
        #pragma unroll
        for (int j = 0; j < 16; j++) {
            keep[j] = (m[tid * 16 + j] == 0.0f) ? 1 : 0;
            c += keep[j];
        }
        cnts[tid] = c;
        __syncthreads();
        if (tid == 0) {
            int acc = 0;
            for (int i = 0; i < 128; i++) { int t = cnts[i]; cnts[i] = acc; acc += t; }
            g_Cnt[b] = acc;
        }
        __syncthreads();
        int o = cnts[tid];
        #pragma unroll
        for (int j = 0; j < 16; j++)
            if (keep[j]) g_Idx[b * SEQ + (o++)] = tid * 16 + j;
        __syncthreads();
        const int cnt = g_Cnt[b];
        for (int i = tid; i < SEQ; i += 128) {
            g_Mc[b * SEQ + i] = __float2half_rn(i < cnt ? 1.0f : 0.0f);
            if (i >= cnt) g_Idx[b * SEQ + i] = 0;
        }
        __syncthreads();
    }

    // ---- W transpose/convert: 16 of 4096 (32x32) tiles ----
    float* s = (float*)sm;   // 32*33 floats
    #pragma unroll 1
    for (int i = 0; i < 16; ++i) {
        const int tt  = bid * 16 + i;
        const int z   = tt >> 10;
        const int rem = tt & 1023;
        const int n0  = (rem & 31) * 32;
        const int k0  = (rem >> 5) * 32;
        const float* W = (z == 0) ? Wq : (z == 1) ? Wk : (z == 2) ? Wv : Wo;
        __half* T = g_Wt + (size_t)z * HID * HID;
        #pragma unroll
        for (int j = 0; j < 8; j++) {
            int idx = tid + j * 128;
            int k = idx >> 5, n = idx & 31;
            s[k * 33 + n] = W[(size_t)(k0 + k) * HID + n0 + n];
        }
        __syncthreads();
        #pragma unroll
        for (int j = 0; j < 8; j++) {
            int idx = tid + j * 128;
            int n = idx >> 5, k = idx & 31;
            T[(size_t)(n0 + n) * HID + k0 + k] = __float2half_rn(s[k * 33 + n]);
        }
        __syncthreads();
    }

    // ---- X convert: 16 rows ----
    #pragma unroll 1
    for (int r = bid * 16; r < bid * 16 + 16; ++r) {
        const float4* s4 = (const float4*)(x + (size_t)r * HID);
        uint2* d = (uint2*)(g_X + (size_t)r * HID);
        #pragma unroll
        for (int i = 0; i < 2; ++i) {
            float4 v = s4[tid * 2 + i];
            d[tid * 2 + i] = make_uint2(packh(v.x, v.y), packh(v.z, v.w));
        }
    }
}

// ---------------- fused mega kernel: prepass | KV | Q | attn | out ----------
#define PRE 256

__global__ __launch_bounds__(128, 2)
void mega(const float* __restrict__ x, const float* __restrict__ mask,
          const float* __restrict__ Wq, const float* __restrict__ bq,
          const float* __restrict__ Wk, const float* __restrict__ bk,
          const float* __restrict__ Wv, const float* __restrict__ bv,
          const float* __restrict__ Wo, const float* __restrict__ bo,
          float* __restrict__ out)
{
    const int bid = blockIdx.x;
    const int tid = threadIdx.x;

    if (bid < PRE) {                       // ---- prepass ----
        prepass_body(bid, x, mask, Wq, Wk, Wv, Wo);
        __syncthreads();
        __threadfence();
        if (tid == 0) atomicAdd(&g_Sync[0], 1);
    } else if (bid < PRE + 512) {          // ---- K/V projections ----
        if (tid == 0) spin_ge(&g_Sync[0], PRE);
        __syncthreads();
        const int r2  = bid - PRE;
        const int z   = r2 >> 8;           // 0=K, 1=V
        const int r   = r2 & 255;
        const int b   = r >> 7;
        const int rem = r & 127;
        const int my  = rem >> 3;
        const int xc  = rem & 7;
        const int cnt = g_Cnt[b];
        const int pad = (cnt + 127) & ~127;
        if (my * 128 < pad) {
            __half* Ch = (z ? g_V : g_K) + (size_t)b * HEADS * SEQ * DH;
            hmma_gemm(g_X + (size_t)b * SEQ * HID,
                      g_Wt + (size_t)(z + 1) * HID * HID,
                      z ? bv : bk, 1.0f, nullptr, Ch, 2,
                      my * 128, xc * 128, g_Idx + b * SEQ, cnt);
        }
        __syncthreads();
        __threadfence();
        if (tid == 0) atomicAdd(&g_Sync[1 + b], 1);
    } else if (bid < PRE + 768) {          // ---- Q projection ----
        if (tid == 0) spin_ge(&g_Sync[0], PRE);
        __syncthreads();
        const int r = bid - (PRE + 512);
        hmma_gemm(g_X, g_Wt, bq, SCALE_L2, nullptr, g_Q, 1,
                  (r >> 3) * 128, (r & 7) * 128, nullptr, 0);
        __syncthreads();
        __threadfence();
        if (tid == 0) atomicExch(&g_Sync[3 + r], 1);
    } else if (bid < PRE + 1280) {         // ---- attention ----
        const int r  = bid - (PRE + 768);
        const int b  = r >> 8;
        const int h  = (r >> 4) & 15;
        const int qx = r & 15;
        if (tid == 0) {
            spin_ge(&g_Sync[3 + (b * 16 + qx) * 8 + (h >> 1)], 1);
            spin_ge(&g_Sync[1 + b], 256);
        }
        __syncthreads();
        attn_body(b, h, qx * 128);
        __syncthreads();
        __threadfence();
        if (tid == 0) atomicAdd(&g_Sync[259 + b * 16 + qx], 1);
    } else {                               // ---- output projection ----
        const int r = bid - (PRE + 1280);
        const int y = r >> 3;
        if (tid == 0) spin_ge(&g_Sync[259 + y], 16);
        __syncthreads();
        hmma_gemm(g_O, g_Wt + (size_t)3 * HID * HID, bo, 1.0f, out, nullptr, 0,
                  y * 128, (r & 7) * 128, nullptr, 0);
    }
}

// ---------------------------------------------------------------------------
extern "C" void kernel_launch(void* const* d_in, const int* in_sizes, int n_in,
                              void* d_out, int out_size)
{
    (void)in_sizes; (void)n_in; (void)out_size;
    const float* x    = (const float*)d_in[0];
    const float* mask = (const float*)d_in[1];
    const float* Wq   = (const float*)d_in[2];
    const float* bq   = (const float*)d_in[3];
    const float* Wk   = (const float*)d_in[4];
    const float* bk   = (const float*)d_in[5];
    const float* Wv   = (const float*)d_in[6];
    const float* bv   = (const float*)d_in[7];
    const float* Wo   = (const float*)d_in[8];
    const float* bo   = (const float*)d_in[9];
    float* out = (float*)d_out;

    int* syncp;
    cudaGetSymbolAddress((void**)&syncp, g_Sync);
    cudaMemsetAsync(syncp, 0, 512 * sizeof(int));

    cudaFuncSetAttribute(mega, cudaFuncAttributeMaxDynamicSharedMemorySize, GEMM_SMEM);
    mega<<<PRE + 1536, 128, GEMM_SMEM>>>(x, mask, Wq, bq, Wk, bk, Wv, bv, Wo, bo, out);
}